// round 15
// baseline (speedup 1.0000x reference)
#include <cuda_runtime.h>
#include <cuda_bf16.h>
#include <math.h>
#include <stdint.h>

// Problem constants (shapes fixed by the dataset).
#define DIM   256
#define MAXN  100000
#define MAXE  800000
#define SCANB 1024
#define MAXBLK 128          // >= ceil(MAXN/SCANB) = 98

// -------- device-global scratch (allocation-free workaround) --------
__device__ float g_support[MAXN * DIM];   // x @ W
__device__ int   g_counts[MAXN];
__device__ int   g_scan[MAXN];
__device__ int   g_rowptr[MAXN + 1];
__device__ int   g_cursor[MAXN];
__device__ int   g_bsum[MAXBLK];
__device__ int   g_esrc[MAXE];
__device__ float g_eval[MAXE];

// ---------------- CSR construction ----------------
__global__ void k_zero_counts(int n) {
    int i = blockIdx.x * blockDim.x + threadIdx.x;
    if (i < n) g_counts[i] = 0;
}

__global__ void k_hist(const int* __restrict__ dst, int E) {
    int e = blockIdx.x * blockDim.x + threadIdx.x;
    if (e < E) atomicAdd(&g_counts[dst[e]], 1);
}

__global__ void k_scan_block(int n) {
    __shared__ int s[SCANB];
    int t = threadIdx.x;
    int gid = blockIdx.x * SCANB + t;
    int v = (gid < n) ? g_counts[gid] : 0;
    s[t] = v;
    __syncthreads();
    #pragma unroll
    for (int off = 1; off < SCANB; off <<= 1) {
        int x = (t >= off) ? s[t - off] : 0;
        __syncthreads();
        s[t] += x;
        __syncthreads();
    }
    if (gid < n) g_scan[gid] = s[t];
    if (t == SCANB - 1) g_bsum[blockIdx.x] = s[t];
}

__global__ void k_scan_sums(int nb) {
    __shared__ int s[MAXBLK];
    int t = threadIdx.x;                 // 128 threads
    int v = (t < nb) ? g_bsum[t] : 0;
    s[t] = v;
    __syncthreads();
    #pragma unroll
    for (int off = 1; off < MAXBLK; off <<= 1) {
        int x = (t >= off) ? s[t - off] : 0;
        __syncthreads();
        s[t] += x;
        __syncthreads();
    }
    if (t < nb) g_bsum[t] = s[t] - v;    // exclusive
}

__global__ void k_finalize_rowptr(int n) {
    int i = blockIdx.x * blockDim.x + threadIdx.x;
    if (i < n) {
        g_rowptr[i + 1] = g_scan[i] + g_bsum[i >> 10];
        int rp0 = (i == 0) ? 0 : (g_scan[i - 1] + g_bsum[(i - 1) >> 10]);
        g_cursor[i] = rp0;
        if (i == 0) g_rowptr[0] = 0;
    }
}

__global__ void k_fill(const int* __restrict__ dst, const int* __restrict__ src,
                       const float* __restrict__ av, const float* __restrict__ aw, int E) {
    int e = blockIdx.x * blockDim.x + threadIdx.x;
    if (e < E) {
        int d = dst[e];
        int p = atomicAdd(&g_cursor[d], 1);
        g_esrc[p] = src[e];
        g_eval[p] = av[e] + aw[e];
    }
}

// ---------------- GEMM: support = x @ W  (3xBF16, reg-staged pipeline) ----
// 128x128 block tile, BK=32, 256 threads = 8 warps in 2(M) x 4(N).
// Tile k+1 global loads issue right after sync, overlapping tile k's MMAs.

__device__ __forceinline__ uint32_t pack_bf16(float a, float b) {
    __nv_bfloat162 h = __floats2bfloat162_rn(a, b);
    return *reinterpret_cast<uint32_t*>(&h);
}
__device__ __forceinline__ float bf16_hi_f(float a) {
    return __bfloat162float(__float2bfloat16_rn(a));
}

__device__ __forceinline__ void mma_bf16(float c[4], uint32_t a0, uint32_t a1,
                                         uint32_t a2, uint32_t a3,
                                         uint32_t b0, uint32_t b1) {
    asm volatile(
        "mma.sync.aligned.m16n8k16.row.col.f32.bf16.bf16.f32 "
        "{%0,%1,%2,%3}, {%4,%5,%6,%7}, {%8,%9}, {%0,%1,%2,%3};"
        : "+f"(c[0]), "+f"(c[1]), "+f"(c[2]), "+f"(c[3])
        : "r"(a0), "r"(a1), "r"(a2), "r"(a3), "r"(b0), "r"(b1));
}

#define GBM 128
#define GBN 128
#define GBK 32
#define KP  (GBK / 2)      // 16 k-pairs
#define A_PITCH 20         // u32 pitch ≡ 4 (mod 32): conflict-free A frag loads
#define B_PITCH 136        // u32 pitch ≡ 8 (mod 32): conflict-free B frag loads

__global__ __launch_bounds__(256) void k_gemm_bf16(const float* __restrict__ X,
                                                   const float* __restrict__ W, int Nrows) {
    __shared__ uint32_t Ash[GBM][A_PITCH];
    __shared__ uint32_t Asl[GBM][A_PITCH];
    __shared__ uint32_t Bsh[KP][B_PITCH];
    __shared__ uint32_t Bsl[KP][B_PITCH];

    const int tid  = threadIdx.x;
    const int lane = tid & 31;
    const int wid  = tid >> 5;
    const int warp_m = wid >> 2;        // 0..1
    const int warp_n = wid & 3;         // 0..3
    const int block_m = blockIdx.x * GBM;
    const int block_n = blockIdx.y * GBN;
    const int g  = lane >> 2;           // 0..7
    const int tg = lane & 3;            // 0..3

    float acc[4][4][4];
    #pragma unroll
    for (int i = 0; i < 4; i++)
        #pragma unroll
        for (int j = 0; j < 4; j++)
            #pragma unroll
            for (int r = 0; r < 4; r++) acc[i][j][r] = 0.0f;

    // Per-thread staged tile registers.
    float4 aS[4];          // A: 4 float4 per thread
    float4 bS0[2], bS1[2]; // B: (w0,w1) x 2 iterations

    // Precomputed per-thread load coordinates.
    int a_row[4], a_k4[4];
    #pragma unroll
    for (int l = 0; l < 4; l++) {
        int idx = tid + l * 256;
        a_row[l] = idx >> 3;
        a_k4[l]  = idx & 7;
    }
    int b_kp[2], b_n4[2];
    #pragma unroll
    for (int l = 0; l < 2; l++) {
        int idx = tid + l * 256;
        b_kp[l] = idx >> 5;
        b_n4[l] = idx & 31;
    }

    // ---- Preload tile 0 ----
    #pragma unroll
    for (int l = 0; l < 4; l++) {
        int grow = block_m + a_row[l];
        aS[l] = make_float4(0.f, 0.f, 0.f, 0.f);
        if (grow < Nrows)
            aS[l] = *reinterpret_cast<const float4*>(&X[(size_t)grow * DIM + a_k4[l] * 4]);
    }
    #pragma unroll
    for (int l = 0; l < 2; l++) {
        bS0[l] = *reinterpret_cast<const float4*>(&W[(size_t)(2 * b_kp[l])     * DIM + block_n + b_n4[l] * 4]);
        bS1[l] = *reinterpret_cast<const float4*>(&W[(size_t)(2 * b_kp[l] + 1) * DIM + block_n + b_n4[l] * 4]);
    }

    for (int k0 = 0; k0 < DIM; k0 += GBK) {
        // ---- Convert + store staged tile to smem ----
        #pragma unroll
        for (int l = 0; l < 4; l++) {
            float4 a = aS[l];
            int r = a_row[l], k4 = a_k4[l];
            float hx = bf16_hi_f(a.x), hy = bf16_hi_f(a.y), hz = bf16_hi_f(a.z), hw = bf16_hi_f(a.w);
            Ash[r][2 * k4 + 0] = pack_bf16(hx, hy);
            Ash[r][2 * k4 + 1] = pack_bf16(hz, hw);
            Asl[r][2 * k4 + 0] = pack_bf16(a.x - hx, a.y - hy);
            Asl[r][2 * k4 + 1] = pack_bf16(a.z - hz, a.w - hw);
        }
        #pragma unroll
        for (int l = 0; l < 2; l++) {
            int kp = b_kp[l], n4 = b_n4[l];
            float a0[4] = {bS0[l].x, bS0[l].y, bS0[l].z, bS0[l].w};
            float a1[4] = {bS1[l].x, bS1[l].y, bS1[l].z, bS1[l].w};
            #pragma unroll
            for (int j = 0; j < 4; j++) {
                float h0 = bf16_hi_f(a0[j]);
                float h1 = bf16_hi_f(a1[j]);
                Bsh[kp][n4 * 4 + j] = pack_bf16(h0, h1);
                Bsl[kp][n4 * 4 + j] = pack_bf16(a0[j] - h0, a1[j] - h1);
            }
        }
        __syncthreads();

        // ---- Issue next tile's global loads (latency hides behind MMAs) ----
        if (k0 + GBK < DIM) {
            int kn = k0 + GBK;
            #pragma unroll
            for (int l = 0; l < 4; l++) {
                int grow = block_m + a_row[l];
                aS[l] = make_float4(0.f, 0.f, 0.f, 0.f);
                if (grow < Nrows)
                    aS[l] = *reinterpret_cast<const float4*>(&X[(size_t)grow * DIM + kn + a_k4[l] * 4]);
            }
            #pragma unroll
            for (int l = 0; l < 2; l++) {
                bS0[l] = *reinterpret_cast<const float4*>(&W[(size_t)(kn + 2 * b_kp[l])     * DIM + block_n + b_n4[l] * 4]);
                bS1[l] = *reinterpret_cast<const float4*>(&W[(size_t)(kn + 2 * b_kp[l] + 1) * DIM + block_n + b_n4[l] * 4]);
            }
        }

        // ---- MMAs over the smem tile ----
        #pragma unroll
        for (int kc = 0; kc < KP; kc += 8) {   // two k16 chunks per BK=32
            uint32_t fah[4][4], fal[4][4];
            #pragma unroll
            for (int mt = 0; mt < 4; mt++) {
                int m = warp_m * 64 + mt * 16 + g;
                fah[mt][0] = Ash[m][kc + tg];
                fah[mt][1] = Ash[m + 8][kc + tg];
                fah[mt][2] = Ash[m][kc + tg + 4];
                fah[mt][3] = Ash[m + 8][kc + tg + 4];
                fal[mt][0] = Asl[m][kc + tg];
                fal[mt][1] = Asl[m + 8][kc + tg];
                fal[mt][2] = Asl[m][kc + tg + 4];
                fal[mt][3] = Asl[m + 8][kc + tg + 4];
            }
            uint32_t fbh[4][2], fbl[4][2];
            #pragma unroll
            for (int nt = 0; nt < 4; nt++) {
                int n = warp_n * 32 + nt * 8 + g;
                fbh[nt][0] = Bsh[kc + tg][n];
                fbh[nt][1] = Bsh[kc + tg + 4][n];
                fbl[nt][0] = Bsl[kc + tg][n];
                fbl[nt][1] = Bsl[kc + tg + 4][n];
            }
            #pragma unroll
            for (int mt = 0; mt < 4; mt++)
                #pragma unroll
                for (int nt = 0; nt < 4; nt++) {
                    mma_bf16(acc[mt][nt], fal[mt][0], fal[mt][1], fal[mt][2], fal[mt][3],
                             fbh[nt][0], fbh[nt][1]);
                    mma_bf16(acc[mt][nt], fah[mt][0], fah[mt][1], fah[mt][2], fah[mt][3],
                             fbl[nt][0], fbl[nt][1]);
                    mma_bf16(acc[mt][nt], fah[mt][0], fah[mt][1], fah[mt][2], fah[mt][3],
                             fbh[nt][0], fbh[nt][1]);
                }
        }
        __syncthreads();
    }

    // Epilogue: write 64x32 warp tile
    #pragma unroll
    for (int mt = 0; mt < 4; mt++) {
        int r0 = block_m + warp_m * 64 + mt * 16 + g;
        #pragma unroll
        for (int nt = 0; nt < 4; nt++) {
            int c = block_n + warp_n * 32 + nt * 8 + 2 * tg;
            if (r0 < Nrows)
                *reinterpret_cast<float2*>(&g_support[(size_t)r0 * DIM + c]) =
                    make_float2(acc[mt][nt][0], acc[mt][nt][1]);
            if (r0 + 8 < Nrows)
                *reinterpret_cast<float2*>(&g_support[(size_t)(r0 + 8) * DIM + c]) =
                    make_float2(acc[mt][nt][2], acc[mt][nt][3]);
        }
    }
}

// ---------------- SpMM + fused L2 normalize (warp-per-row, R14-proven) ----
__global__ __launch_bounds__(256) void k_spmm_norm(float* __restrict__ out, int n) {
    const int lane = threadIdx.x & 31;
    const int row  = blockIdx.x * 8 + (threadIdx.x >> 5);
    if (row >= n) return;

    const int beg = g_rowptr[row];
    const int end = g_rowptr[row + 1];

    float4 p0 = make_float4(0.f, 0.f, 0.f, 0.f);
    float4 p1 = make_float4(0.f, 0.f, 0.f, 0.f);
    float4 q0 = make_float4(0.f, 0.f, 0.f, 0.f);
    float4 q1 = make_float4(0.f, 0.f, 0.f, 0.f);

    int e = beg;
    for (; e + 1 < end; e += 2) {
        int   s0 = __ldg(&g_esrc[e]);
        int   s1 = __ldg(&g_esrc[e + 1]);
        float v0 = __ldg(&g_eval[e]);
        float v1 = __ldg(&g_eval[e + 1]);
        const float4* r0 = reinterpret_cast<const float4*>(&g_support[(size_t)s0 * DIM]);
        const float4* r1 = reinterpret_cast<const float4*>(&g_support[(size_t)s1 * DIM]);
        float4 x0 = r0[lane];
        float4 x1 = r0[lane + 32];
        float4 y0 = r1[lane];
        float4 y1 = r1[lane + 32];
        p0.x = fmaf(v0, x0.x, p0.x); p0.y = fmaf(v0, x0.y, p0.y);
        p0.z = fmaf(v0, x0.z, p0.z); p0.w = fmaf(v0, x0.w, p0.w);
        p1.x = fmaf(v0, x1.x, p1.x); p1.y = fmaf(v0, x1.y, p1.y);
        p1.z = fmaf(v0, x1.z, p1.z); p1.w = fmaf(v0, x1.w, p1.w);
        q0.x = fmaf(v1, y0.x, q0.x); q0.y = fmaf(v1, y0.y, q0.y);
        q0.z = fmaf(v1, y0.z, q0.z); q0.w = fmaf(v1, y0.w, q0.w);
        q1.x = fmaf(v1, y1.x, q1.x); q1.y = fmaf(v1, y1.y, q1.y);
        q1.z = fmaf(v1, y1.z, q1.z); q1.w = fmaf(v1, y1.w, q1.w);
    }
    if (e < end) {
        int   s0 = __ldg(&g_esrc[e]);
        float v0 = __ldg(&g_eval[e]);
        const float4* r0 = reinterpret_cast<const float4*>(&g_support[(size_t)s0 * DIM]);
        float4 x0 = r0[lane];
        float4 x1 = r0[lane + 32];
        p0.x = fmaf(v0, x0.x, p0.x); p0.y = fmaf(v0, x0.y, p0.y);
        p0.z = fmaf(v0, x0.z, p0.z); p0.w = fmaf(v0, x0.w, p0.w);
        p1.x = fmaf(v0, x1.x, p1.x); p1.y = fmaf(v0, x1.y, p1.y);
        p1.z = fmaf(v0, x1.z, p1.z); p1.w = fmaf(v0, x1.w, p1.w);
    }
    float4 a0 = make_float4(p0.x + q0.x, p0.y + q0.y, p0.z + q0.z, p0.w + q0.w);
    float4 a1 = make_float4(p1.x + q1.x, p1.y + q1.y, p1.z + q1.z, p1.w + q1.w);

    float ss = a0.x * a0.x + a0.y * a0.y + a0.z * a0.z + a0.w * a0.w
             + a1.x * a1.x + a1.y * a1.y + a1.z * a1.z + a1.w * a1.w;
    #pragma unroll
    for (int o = 16; o > 0; o >>= 1)
        ss += __shfl_xor_sync(0xFFFFFFFF, ss, o);

    float inv = 1.0f / fmaxf(sqrtf(ss), 1e-12f);
    float4* dst = reinterpret_cast<float4*>(&out[(size_t)row * DIM]);
    dst[lane]      = make_float4(a0.x * inv, a0.y * inv, a0.z * inv, a0.w * inv);
    dst[lane + 32] = make_float4(a1.x * inv, a1.y * inv, a1.z * inv, a1.w * inv);
}

// ---------------- launch ----------------
extern "C" void kernel_launch(void* const* d_in, const int* in_sizes, int n_in,
                              void* d_out, int out_size) {
    const float* x  = (const float*)d_in[0];   // [N, 256]
    const float* W  = (const float*)d_in[1];   // [256, 256]
    const float* av = (const float*)d_in[2];   // [E]
    const float* aw = (const float*)d_in[3];   // [E]
    const int*   ei = (const int*)  d_in[4];   // [2, E]: dst row, then src row
    float* out = (float*)d_out;

    int N = in_sizes[0] / DIM;
    int E = in_sizes[2];
    const int* dst = ei;
    const int* src = ei + E;

    int nb = (N + SCANB - 1) / SCANB;

    // CSR launches 1-3
    k_zero_counts<<<(N + 255) / 256, 256>>>(N);
    k_hist<<<(E + 255) / 256, 256>>>(dst, E);
    k_scan_block<<<nb, SCANB>>>(N);

    // GEMM — launch #4 (ncu capture slot)
    dim3 ggrid((N + GBM - 1) / GBM, DIM / GBN);
    k_gemm_bf16<<<ggrid, 256>>>(x, W, N);

    // CSR launches 5-7
    k_scan_sums<<<1, MAXBLK>>>(nb);
    k_finalize_rowptr<<<(N + 255) / 256, 256>>>(N);
    k_fill<<<(E + 255) / 256, 256>>>(dst, src, av, aw, E);

    // Aggregate + normalize (warp-per-row)
    k_spmm_norm<<<(N + 7) / 8, 256>>>(out, N);
}

// round 16
// speedup vs baseline: 1.0411x; 1.0411x over previous
#include <cuda_runtime.h>
#include <cuda_bf16.h>
#include <math.h>
#include <stdint.h>

// Problem constants (shapes fixed by the dataset).
#define DIM   256
#define MAXN  100000
#define MAXE  800000
#define SCANB 1024
#define MAXBLK 128          // >= ceil(MAXN/SCANB) = 98

// -------- device-global scratch (allocation-free workaround) --------
__device__ float g_support[MAXN * DIM];   // x @ W
__device__ int   g_counts[MAXN];
__device__ int   g_scan[MAXN];
__device__ int   g_rowptr[MAXN + 1];
__device__ int   g_cursor[MAXN];
__device__ int   g_bsum[MAXBLK];
__device__ int2  g_edge[MAXE];            // packed (src, val-bits) per edge

// ---------------- CSR construction ----------------
__global__ void k_zero_counts(int n) {
    int i = blockIdx.x * blockDim.x + threadIdx.x;
    if (i < n) g_counts[i] = 0;
}

__global__ void k_hist(const int* __restrict__ dst, int E) {
    int e = blockIdx.x * blockDim.x + threadIdx.x;
    if (e < E) atomicAdd(&g_counts[dst[e]], 1);
}

__global__ void k_scan_block(int n) {
    __shared__ int s[SCANB];
    int t = threadIdx.x;
    int gid = blockIdx.x * SCANB + t;
    int v = (gid < n) ? g_counts[gid] : 0;
    s[t] = v;
    __syncthreads();
    #pragma unroll
    for (int off = 1; off < SCANB; off <<= 1) {
        int x = (t >= off) ? s[t - off] : 0;
        __syncthreads();
        s[t] += x;
        __syncthreads();
    }
    if (gid < n) g_scan[gid] = s[t];
    if (t == SCANB - 1) g_bsum[blockIdx.x] = s[t];
}

// finalize with in-block scan of the (<=128) block sums (scan_sums fused in).
// g_bsum is read-only here; the exclusive prefix lives in each block's smem.
__global__ void k_finalize_rowptr(int n, int nb) {
    __shared__ int s[MAXBLK];
    int t = threadIdx.x;                 // 256 threads; first 128 do the scan
    if (t < MAXBLK) {
        int v = (t < nb) ? g_bsum[t] : 0;
        s[t] = v;
    }
    __syncthreads();
    #pragma unroll
    for (int off = 1; off < MAXBLK; off <<= 1) {
        int x = (t < MAXBLK && t >= off) ? s[t - off] : 0;
        __syncthreads();
        if (t < MAXBLK) s[t] += x;
        __syncthreads();
    }
    // s[] now inclusive; exclusive(j) = s[j] - bsum[j]
    int i = blockIdx.x * blockDim.x + t;
    if (i < n) {
        int ex_i  = s[i >> 10] - g_bsum[i >> 10];
        g_rowptr[i + 1] = g_scan[i] + ex_i;
        int rp0;
        if (i == 0) rp0 = 0;
        else {
            int j = (i - 1) >> 10;
            rp0 = g_scan[i - 1] + (s[j] - g_bsum[j]);
        }
        g_cursor[i] = rp0;
        if (i == 0) g_rowptr[0] = 0;
    }
}

__global__ void k_fill(const int* __restrict__ dst, const int* __restrict__ src,
                       const float* __restrict__ av, const float* __restrict__ aw, int E) {
    int e = blockIdx.x * blockDim.x + threadIdx.x;
    if (e < E) {
        int d = dst[e];
        int p = atomicAdd(&g_cursor[d], 1);
        float v = av[e] + aw[e];
        g_edge[p] = make_int2(src[e], __float_as_int(v));   // one 8B scattered write
    }
}

// ---------------- GEMM: support = x @ W  (3xBF16 tensor-core, R14-proven) ----
// 128x128 block tile, BK=32, 256 threads = 8 warps in 2(M) x 4(N).
// Measured: 181us, 127 regs, 2 CTAs/SM, tensor 41%. FROZEN.

__device__ __forceinline__ uint32_t pack_bf16(float a, float b) {
    __nv_bfloat162 h = __floats2bfloat162_rn(a, b);
    return *reinterpret_cast<uint32_t*>(&h);
}
__device__ __forceinline__ float bf16_hi_f(float a) {
    return __bfloat162float(__float2bfloat16_rn(a));
}

__device__ __forceinline__ void mma_bf16(float c[4], uint32_t a0, uint32_t a1,
                                         uint32_t a2, uint32_t a3,
                                         uint32_t b0, uint32_t b1) {
    asm volatile(
        "mma.sync.aligned.m16n8k16.row.col.f32.bf16.bf16.f32 "
        "{%0,%1,%2,%3}, {%4,%5,%6,%7}, {%8,%9}, {%0,%1,%2,%3};"
        : "+f"(c[0]), "+f"(c[1]), "+f"(c[2]), "+f"(c[3])
        : "r"(a0), "r"(a1), "r"(a2), "r"(a3), "r"(b0), "r"(b1));
}

#define GBM 128
#define GBN 128
#define GBK 32
#define KP  (GBK / 2)      // 16 k-pairs
#define A_PITCH 20         // u32 pitch ≡ 4 (mod 32): conflict-free A frag loads
#define B_PITCH 136        // u32 pitch ≡ 8 (mod 32): conflict-free B frag loads

__global__ __launch_bounds__(256) void k_gemm_bf16(const float* __restrict__ X,
                                                   const float* __restrict__ W, int Nrows) {
    __shared__ uint32_t Ash[GBM][A_PITCH];
    __shared__ uint32_t Asl[GBM][A_PITCH];
    __shared__ uint32_t Bsh[KP][B_PITCH];
    __shared__ uint32_t Bsl[KP][B_PITCH];

    const int tid  = threadIdx.x;
    const int lane = tid & 31;
    const int wid  = tid >> 5;
    const int warp_m = wid >> 2;        // 0..1
    const int warp_n = wid & 3;         // 0..3
    const int block_m = blockIdx.x * GBM;
    const int block_n = blockIdx.y * GBN;
    const int g  = lane >> 2;           // 0..7
    const int tg = lane & 3;            // 0..3

    float acc[4][4][4];
    #pragma unroll
    for (int i = 0; i < 4; i++)
        #pragma unroll
        for (int j = 0; j < 4; j++)
            #pragma unroll
            for (int r = 0; r < 4; r++) acc[i][j][r] = 0.0f;

    for (int k0 = 0; k0 < DIM; k0 += GBK) {
        #pragma unroll
        for (int l = 0; l < 4; l++) {
            int idx = tid + l * 256;        // 0..1023
            int r   = idx >> 3;             // 8 float4 per row
            int k4  = idx & 7;
            int grow = block_m + r;
            float4 a = make_float4(0.f, 0.f, 0.f, 0.f);
            if (grow < Nrows)
                a = *reinterpret_cast<const float4*>(&X[(size_t)grow * DIM + k0 + k4 * 4]);
            float hx = bf16_hi_f(a.x), hy = bf16_hi_f(a.y), hz = bf16_hi_f(a.z), hw = bf16_hi_f(a.w);
            Ash[r][2 * k4 + 0] = pack_bf16(hx, hy);
            Ash[r][2 * k4 + 1] = pack_bf16(hz, hw);
            Asl[r][2 * k4 + 0] = pack_bf16(a.x - hx, a.y - hy);
            Asl[r][2 * k4 + 1] = pack_bf16(a.z - hz, a.w - hw);
        }
        #pragma unroll
        for (int l = 0; l < 2; l++) {
            int idx = tid + l * 256;        // 0..511
            int kp  = idx >> 5;             // 0..15
            int n4  = idx & 31;
            float4 w0 = *reinterpret_cast<const float4*>(&W[(size_t)(k0 + 2 * kp)     * DIM + block_n + n4 * 4]);
            float4 w1 = *reinterpret_cast<const float4*>(&W[(size_t)(k0 + 2 * kp + 1) * DIM + block_n + n4 * 4]);
            float a0[4] = {w0.x, w0.y, w0.z, w0.w};
            float a1[4] = {w1.x, w1.y, w1.z, w1.w};
            #pragma unroll
            for (int j = 0; j < 4; j++) {
                float h0 = bf16_hi_f(a0[j]);
                float h1 = bf16_hi_f(a1[j]);
                Bsh[kp][n4 * 4 + j] = pack_bf16(h0, h1);
                Bsl[kp][n4 * 4 + j] = pack_bf16(a0[j] - h0, a1[j] - h1);
            }
        }
        __syncthreads();

        #pragma unroll
        for (int kc = 0; kc < KP; kc += 8) {   // two k16 chunks per BK=32
            uint32_t fah[4][4], fal[4][4];
            #pragma unroll
            for (int mt = 0; mt < 4; mt++) {
                int m = warp_m * 64 + mt * 16 + g;
                fah[mt][0] = Ash[m][kc + tg];
                fah[mt][1] = Ash[m + 8][kc + tg];
                fah[mt][2] = Ash[m][kc + tg + 4];
                fah[mt][3] = Ash[m + 8][kc + tg + 4];
                fal[mt][0] = Asl[m][kc + tg];
                fal[mt][1] = Asl[m + 8][kc + tg];
                fal[mt][2] = Asl[m][kc + tg + 4];
                fal[mt][3] = Asl[m + 8][kc + tg + 4];
            }
            uint32_t fbh[4][2], fbl[4][2];
            #pragma unroll
            for (int nt = 0; nt < 4; nt++) {
                int n = warp_n * 32 + nt * 8 + g;
                fbh[nt][0] = Bsh[kc + tg][n];
                fbh[nt][1] = Bsh[kc + tg + 4][n];
                fbl[nt][0] = Bsl[kc + tg][n];
                fbl[nt][1] = Bsl[kc + tg + 4][n];
            }
            #pragma unroll
            for (int mt = 0; mt < 4; mt++)
                #pragma unroll
                for (int nt = 0; nt < 4; nt++) {
                    mma_bf16(acc[mt][nt], fal[mt][0], fal[mt][1], fal[mt][2], fal[mt][3],
                             fbh[nt][0], fbh[nt][1]);
                    mma_bf16(acc[mt][nt], fah[mt][0], fah[mt][1], fah[mt][2], fah[mt][3],
                             fbl[nt][0], fbl[nt][1]);
                    mma_bf16(acc[mt][nt], fah[mt][0], fah[mt][1], fah[mt][2], fah[mt][3],
                             fbh[nt][0], fbh[nt][1]);
                }
        }
        __syncthreads();
    }

    #pragma unroll
    for (int mt = 0; mt < 4; mt++) {
        int r0 = block_m + warp_m * 64 + mt * 16 + g;
        #pragma unroll
        for (int nt = 0; nt < 4; nt++) {
            int c = block_n + warp_n * 32 + nt * 8 + 2 * tg;
            if (r0 < Nrows)
                *reinterpret_cast<float2*>(&g_support[(size_t)r0 * DIM + c]) =
                    make_float2(acc[mt][nt][0], acc[mt][nt][1]);
            if (r0 + 8 < Nrows)
                *reinterpret_cast<float2*>(&g_support[(size_t)(r0 + 8) * DIM + c]) =
                    make_float2(acc[mt][nt][2], acc[mt][nt][3]);
        }
    }
}

// ---------------- SpMM + fused L2 normalize (warp-per-row, R14-proven) ----
__global__ __launch_bounds__(256) void k_spmm_norm(float* __restrict__ out, int n) {
    const int lane = threadIdx.x & 31;
    const int row  = blockIdx.x * 8 + (threadIdx.x >> 5);
    if (row >= n) return;

    const int beg = g_rowptr[row];
    const int end = g_rowptr[row + 1];

    float4 p0 = make_float4(0.f, 0.f, 0.f, 0.f);
    float4 p1 = make_float4(0.f, 0.f, 0.f, 0.f);
    float4 q0 = make_float4(0.f, 0.f, 0.f, 0.f);
    float4 q1 = make_float4(0.f, 0.f, 0.f, 0.f);

    int e = beg;
    for (; e + 1 < end; e += 2) {
        int2 e0 = __ldg(&g_edge[e]);
        int2 e1 = __ldg(&g_edge[e + 1]);
        int   s0 = e0.x;
        int   s1 = e1.x;
        float v0 = __int_as_float(e0.y);
        float v1 = __int_as_float(e1.y);
        const float4* r0 = reinterpret_cast<const float4*>(&g_support[(size_t)s0 * DIM]);
        const float4* r1 = reinterpret_cast<const float4*>(&g_support[(size_t)s1 * DIM]);
        float4 x0 = r0[lane];
        float4 x1 = r0[lane + 32];
        float4 y0 = r1[lane];
        float4 y1 = r1[lane + 32];
        p0.x = fmaf(v0, x0.x, p0.x); p0.y = fmaf(v0, x0.y, p0.y);
        p0.z = fmaf(v0, x0.z, p0.z); p0.w = fmaf(v0, x0.w, p0.w);
        p1.x = fmaf(v0, x1.x, p1.x); p1.y = fmaf(v0, x1.y, p1.y);
        p1.z = fmaf(v0, x1.z, p1.z); p1.w = fmaf(v0, x1.w, p1.w);
        q0.x = fmaf(v1, y0.x, q0.x); q0.y = fmaf(v1, y0.y, q0.y);
        q0.z = fmaf(v1, y0.z, q0.z); q0.w = fmaf(v1, y0.w, q0.w);
        q1.x = fmaf(v1, y1.x, q1.x); q1.y = fmaf(v1, y1.y, q1.y);
        q1.z = fmaf(v1, y1.z, q1.z); q1.w = fmaf(v1, y1.w, q1.w);
    }
    if (e < end) {
        int2 e0 = __ldg(&g_edge[e]);
        int   s0 = e0.x;
        float v0 = __int_as_float(e0.y);
        const float4* r0 = reinterpret_cast<const float4*>(&g_support[(size_t)s0 * DIM]);
        float4 x0 = r0[lane];
        float4 x1 = r0[lane + 32];
        p0.x = fmaf(v0, x0.x, p0.x); p0.y = fmaf(v0, x0.y, p0.y);
        p0.z = fmaf(v0, x0.z, p0.z); p0.w = fmaf(v0, x0.w, p0.w);
        p1.x = fmaf(v0, x1.x, p1.x); p1.y = fmaf(v0, x1.y, p1.y);
        p1.z = fmaf(v0, x1.z, p1.z); p1.w = fmaf(v0, x1.w, p1.w);
    }
    float4 a0 = make_float4(p0.x + q0.x, p0.y + q0.y, p0.z + q0.z, p0.w + q0.w);
    float4 a1 = make_float4(p1.x + q1.x, p1.y + q1.y, p1.z + q1.z, p1.w + q1.w);

    float ss = a0.x * a0.x + a0.y * a0.y + a0.z * a0.z + a0.w * a0.w
             + a1.x * a1.x + a1.y * a1.y + a1.z * a1.z + a1.w * a1.w;
    #pragma unroll
    for (int o = 16; o > 0; o >>= 1)
        ss += __shfl_xor_sync(0xFFFFFFFF, ss, o);

    float inv = 1.0f / fmaxf(sqrtf(ss), 1e-12f);
    float4* dst = reinterpret_cast<float4*>(&out[(size_t)row * DIM]);
    dst[lane]      = make_float4(a0.x * inv, a0.y * inv, a0.z * inv, a0.w * inv);
    dst[lane + 32] = make_float4(a1.x * inv, a1.y * inv, a1.z * inv, a1.w * inv);
}

// ---------------- launch ----------------
extern "C" void kernel_launch(void* const* d_in, const int* in_sizes, int n_in,
                              void* d_out, int out_size) {
    const float* x  = (const float*)d_in[0];   // [N, 256]
    const float* W  = (const float*)d_in[1];   // [256, 256]
    const float* av = (const float*)d_in[2];   // [E]
    const float* aw = (const float*)d_in[3];   // [E]
    const int*   ei = (const int*)  d_in[4];   // [2, E]: dst row, then src row
    float* out = (float*)d_out;

    int N = in_sizes[0] / DIM;
    int E = in_sizes[2];
    const int* dst = ei;
    const int* src = ei + E;

    int nb = (N + SCANB - 1) / SCANB;

    // CSR launches 1-3
    k_zero_counts<<<(N + 255) / 256, 256>>>(N);
    k_hist<<<(E + 255) / 256, 256>>>(dst, E);
    k_scan_block<<<nb, SCANB>>>(N);

    // GEMM — launch #4 (ncu capture slot)
    dim3 ggrid((N + GBM - 1) / GBM, DIM / GBN);
    k_gemm_bf16<<<ggrid, 256>>>(x, W, N);

    // CSR launches 5-6 (scan_sums fused into finalize)
    k_finalize_rowptr<<<(N + 255) / 256, 256>>>(N, nb);
    k_fill<<<(E + 255) / 256, 256>>>(dst, src, av, aw, E);

    // Aggregate + normalize (warp-per-row)
    k_spmm_norm<<<(N + 7) / 8, 256>>>(out, N);
}